// round 11
// baseline (speedup 1.0000x reference)
#include <cuda_runtime.h>
#include <cuda_bf16.h>

// TimeWarp, single fused kernel, register-resident y-tables (no phase-1a, 1 barrier).
// Block = (b, j-tile of 256, i-group of 32 freq rows) -> grid 4096.
//   Setup:  x-resampled P-tile (<=12 rows x 32 i's) in smem (1 LDG-pair/thread).
//   Stream: each thread computes its chunk's wy/floor(y) in registers, then
//           8 coalesced STG.128 into this block's rows. At HBM write floor.
// B=32, F=128, T=8192, fp32.

#define NB 32
#define NF 128
#define NT 8192
#define TILE_J   256              // j's per block
#define TILE_C   (TILE_J / 4)     // 64 float4-chunks per block
#define TILE_I   32               // freq rows per block
#define MAX_ROWS 12               // y-span over 256 j's <= ~4.1 (+2 lerp +1) -> <=8; 12 safe

__global__ __launch_bounds__(256, 8)
void timewarp_fused(const float* __restrict__ S,
                    const int*   __restrict__ psrc,
                    const int*   __restrict__ pdst,
                    float*       __restrict__ out)
{
    __shared__ float sP[MAX_ROWS * TILE_I];    // x-resampled rows [Ymin..), i-slice only

    const int t  = threadIdx.x;                // 256 threads
    const int jt = blockIdx.x & 31;            // 0..31  j-tile
    const int ig = blockIdx.x >> 5;            // 0..3   i-group
    const int b  = blockIdx.y;                 // 0..31  batch
    const int j_base = jt * TILE_J;
    const int i_base = ig * TILE_I;

    const float s = (float)__ldg(psrc);
    const float d = (float)__ldg(pdst);
    const float rl = s / d;
    const float rr = ((float)NT - s) / ((float)NT - d);

    // y(j) exactly as the reference (monotone nondecreasing in j)
    auto yval = [&](float tf) -> float {
        float idx = (tf < d) ? (tf * rl) : fmaf(tf - d, rr, s);
        idx = fminf(fmaxf(idx, 0.0f), (float)(NT - 1));
        float y = idx * (1.0f / (float)(NT - 1)) * (float)(NF - 1);
        return fminf(fmaxf(y, 0.0f), (float)(NF - 1));
    };

    // Tile row window (computed redundantly by every thread; no smem, no barrier)
    const int Ymin = (int)floorf(yval((float)j_base));
    int nrows = (int)floorf(yval((float)(j_base + TILE_J - 1))) + 3 - Ymin;
    if (nrows > MAX_ROWS) nrows = MAX_ROWS;

    // ---------- build P-tile: x-resample needed rows, this i-slice ----------
    const float* Sb = S + (size_t)b * (size_t)(NF * NT);
    for (int v = t; v < nrows * TILE_I; v += 256) {   // nrows<=8 -> exactly 1 iter/thread
        const int r  = v >> 5;
        const int il = v & (TILE_I - 1);
        const int i  = i_base + il;
        const int rs = min(Ymin + r, NF - 1);         // border clamp / pad rows

        float x_pix = ((float)i / (float)(NF - 1)) * (float)(NT - 1);
        x_pix = fminf(fmaxf(x_pix, 0.0f), (float)(NT - 1));
        const float x0f = floorf(x_pix);
        const int   x0  = (int)x0f;
        const int   x1  = min(x0 + 1, NT - 1);
        const float wx  = x_pix - x0f;

        const float* row = Sb + (size_t)rs * NT;
        const float v0 = __ldg(row + x0);
        const float v1 = __ldg(row + x1);
        sP[v] = fmaf(wx, v1 - v0, v0);
    }
    __syncthreads();                                  // the only barrier

    // ---------- stream TILE_I freq rows x 256 j ----------
    const int tx = t & (TILE_C - 1);                  // chunk within tile (warp-contiguous)
    const int ty = t >> 6;                            // i-offset 0..3

    // Register-resident per-chunk y tables (identical FP sequence to prior rounds)
    float wy0, wy1, wy2, wy3; int Y;
    {
        float y  = yval((float)(j_base + tx * 4));
        float yf = floorf(y);
        wy0 = y - yf;  Y = (int)yf;
        y = yval((float)(j_base + tx * 4 + 1)); wy1 = y - floorf(y);
        y = yval((float)(j_base + tx * 4 + 2)); wy2 = y - floorf(y);
        y = yval((float)(j_base + tx * 4 + 3)); wy3 = y - floorf(y);
    }
    const int rel = Y - Ymin;                         // 0..nrows-3
    const float* pc = sP + rel * TILE_I;

    const bool s1 = wy1 < wy0;                        // floor advanced <=> frac wrapped
    const bool s2 = wy2 < wy0;
    const bool s3 = wy3 < wy0;

    float* obase = out + ((size_t)b * NF + i_base) * (size_t)NT + (size_t)(j_base + tx * 4);

#pragma unroll
    for (int r = 0; r < TILE_I / 4; r++) {            // 8 iterations
        const int il = r * 4 + ty;

        const float pA = pc[il];
        const float pB = pc[TILE_I + il];
        const float pC = pc[2 * TILE_I + il];

        float o0 = fmaf(wy0, pB - pA, pA);
        float l1 = s1 ? pB : pA, h1 = s1 ? pC : pB;
        float l2 = s2 ? pB : pA, h2 = s2 ? pC : pB;
        float l3 = s3 ? pB : pA, h3 = s3 ? pC : pB;
        float o1 = fmaf(wy1, h1 - l1, l1);
        float o2 = fmaf(wy2, h2 - l2, l2);
        float o3 = fmaf(wy3, h3 - l3, l3);

        *reinterpret_cast<float4*>(obase + (size_t)il * NT) =
            make_float4(o0, o1, o2, o3);
    }
}

extern "C" void kernel_launch(void* const* d_in, const int* in_sizes, int n_in,
                              void* d_out, int out_size)
{
    const float* S    = (const float*)d_in[0];
    const int*   psrc = (const int*)d_in[1];
    const int*   pdst = (const int*)d_in[2];
    float*       out  = (float*)d_out;

    dim3 grid((NT / TILE_J) * (NF / TILE_I), NB);     // (32*4) x 32 = 4096 blocks
    timewarp_fused<<<grid, 256>>>(S, psrc, pdst, out);
}

// round 13
// speedup vs baseline: 1.0170x; 1.0170x over previous
#include <cuda_runtime.h>
#include <cuda_bf16.h>

// TimeWarp, single fused kernel, register-resident y-tables, 1 barrier.
// Block = (b, j-tile of 256, i-group of 64 freq rows) -> grid 2048 (halved dispatch ramp).
//   Setup:  x-resampled P-tile (<=12 rows x 64 i's) in smem (<=3 LDG-pairs/thread).
//   Stream: per-thread wy/floor(y) in registers, then 16 coalesced STG.128.
// B=32, F=128, T=8192, fp32.

#define NB 32
#define NF 128
#define NT 8192
#define TILE_J   256              // j's per block
#define TILE_C   (TILE_J / 4)     // 64 float4-chunks per block
#define TILE_I   64               // freq rows per block
#define MAX_ROWS 12               // y-span over 256 j's <= ~4.1 (+2 lerp +1) -> <=8; 12 safe

__global__ __launch_bounds__(256, 8)
void timewarp_fused(const float* __restrict__ S,
                    const int*   __restrict__ psrc,
                    const int*   __restrict__ pdst,
                    float*       __restrict__ out)
{
    __shared__ float sP[MAX_ROWS * TILE_I];    // x-resampled rows [Ymin..), i-slice only

    const int t  = threadIdx.x;                // 256 threads
    const int jt = blockIdx.x & 31;            // 0..31  j-tile
    const int ig = blockIdx.x >> 5;            // 0..1   i-group
    const int b  = blockIdx.y;                 // 0..31  batch
    const int j_base = jt * TILE_J;
    const int i_base = ig * TILE_I;

    const float s = (float)__ldg(psrc);
    const float d = (float)__ldg(pdst);
    const float rl = s / d;
    const float rr = ((float)NT - s) / ((float)NT - d);

    // y(j) exactly as the reference (monotone nondecreasing in j)
    auto yval = [&](float tf) -> float {
        float idx = (tf < d) ? (tf * rl) : fmaf(tf - d, rr, s);
        idx = fminf(fmaxf(idx, 0.0f), (float)(NT - 1));
        float y = idx * (1.0f / (float)(NT - 1)) * (float)(NF - 1);
        return fminf(fmaxf(y, 0.0f), (float)(NF - 1));
    };

    // Tile row window (computed redundantly per thread; no smem, no barrier)
    const int Ymin = (int)floorf(yval((float)j_base));
    int nrows = (int)floorf(yval((float)(j_base + TILE_J - 1))) + 3 - Ymin;
    if (nrows > MAX_ROWS) nrows = MAX_ROWS;

    // ---------- build P-tile: x-resample needed rows, this i-slice ----------
    const float* Sb = S + (size_t)b * (size_t)(NF * NT);
    for (int v = t; v < nrows * TILE_I; v += 256) {   // nrows<=8 -> <=2 iters/thread
        const int r  = v >> 6;
        const int il = v & (TILE_I - 1);
        const int i  = i_base + il;
        const int rs = min(Ymin + r, NF - 1);         // border clamp / pad rows

        float x_pix = ((float)i / (float)(NF - 1)) * (float)(NT - 1);
        x_pix = fminf(fmaxf(x_pix, 0.0f), (float)(NT - 1));
        const float x0f = floorf(x_pix);
        const int   x0  = (int)x0f;
        const int   x1  = min(x0 + 1, NT - 1);
        const float wx  = x_pix - x0f;

        const float* row = Sb + (size_t)rs * NT;
        const float v0 = __ldg(row + x0);
        const float v1 = __ldg(row + x1);
        sP[v] = fmaf(wx, v1 - v0, v0);
    }
    __syncthreads();                                  // the only barrier

    // ---------- stream TILE_I freq rows x 256 j ----------
    const int tx = t & (TILE_C - 1);                  // chunk within tile (warp-contiguous)
    const int ty = t >> 6;                            // i-offset 0..3

    // Register-resident per-chunk y tables (identical FP sequence to prior rounds)
    float wy0, wy1, wy2, wy3; int Y;
    {
        float y  = yval((float)(j_base + tx * 4));
        float yf = floorf(y);
        wy0 = y - yf;  Y = (int)yf;
        y = yval((float)(j_base + tx * 4 + 1)); wy1 = y - floorf(y);
        y = yval((float)(j_base + tx * 4 + 2)); wy2 = y - floorf(y);
        y = yval((float)(j_base + tx * 4 + 3)); wy3 = y - floorf(y);
    }
    const int rel = Y - Ymin;                         // 0..nrows-3
    const float* pc = sP + rel * TILE_I;

    const bool s1 = wy1 < wy0;                        // floor advanced <=> frac wrapped
    const bool s2 = wy2 < wy0;
    const bool s3 = wy3 < wy0;

    float* obase = out + ((size_t)b * NF + i_base) * (size_t)NT + (size_t)(j_base + tx * 4);

#pragma unroll
    for (int r = 0; r < TILE_I / 4; r++) {            // 16 iterations
        const int il = r * 4 + ty;

        const float pA = pc[il];
        const float pB = pc[TILE_I + il];
        const float pC = pc[2 * TILE_I + il];

        float o0 = fmaf(wy0, pB - pA, pA);
        float l1 = s1 ? pB : pA, h1 = s1 ? pC : pB;
        float l2 = s2 ? pB : pA, h2 = s2 ? pC : pB;
        float l3 = s3 ? pB : pA, h3 = s3 ? pC : pB;
        float o1 = fmaf(wy1, h1 - l1, l1);
        float o2 = fmaf(wy2, h2 - l2, l2);
        float o3 = fmaf(wy3, h3 - l3, l3);

        *reinterpret_cast<float4*>(obase + (size_t)il * NT) =
            make_float4(o0, o1, o2, o3);
    }
}

extern "C" void kernel_launch(void* const* d_in, const int* in_sizes, int n_in,
                              void* d_out, int out_size)
{
    const float* S    = (const float*)d_in[0];
    const int*   psrc = (const int*)d_in[1];
    const int*   pdst = (const int*)d_in[2];
    float*       out  = (float*)d_out;

    dim3 grid((NT / TILE_J) * (NF / TILE_I), NB);     // (32*2) x 32 = 2048 blocks
    timewarp_fused<<<grid, 256>>>(S, psrc, pdst, out);
}

// round 14
// speedup vs baseline: 1.1500x; 1.1308x over previous
#include <cuda_runtime.h>
#include <cuda_bf16.h>

// TimeWarp, single fused kernel.
// R11 inner structure (register-resident y-tables, single barrier)
// in R4's launch shape (TILE_I=128 -> grid 1024, __stcs streaming stores).
// B=32, F=128, T=8192, fp32.

#define NB 32
#define NF 128
#define NT 8192
#define TILE_J   256              // j's per block
#define TILE_C   (TILE_J / 4)     // 64 float4-chunks per block
#define MAX_ROWS 12               // y-span over 256 j's <= ~4.1 (+2 lerp +1) -> <=8; 12 safe

__global__ __launch_bounds__(256, 8)
void timewarp_fused(const float* __restrict__ S,
                    const int*   __restrict__ psrc,
                    const int*   __restrict__ pdst,
                    float*       __restrict__ out)
{
    __shared__ float sP[MAX_ROWS * NF];        // x-resampled rows [Ymin..), full i range

    const int t  = threadIdx.x;                // 256 threads
    const int jt = blockIdx.x;                 // 0..31  j-tile
    const int b  = blockIdx.y;                 // 0..31  batch
    const int j_base = jt * TILE_J;

    const float s = (float)__ldg(psrc);
    const float d = (float)__ldg(pdst);
    const float rl = s / d;
    const float rr = ((float)NT - s) / ((float)NT - d);

    // y(j) exactly as the reference (monotone nondecreasing in j)
    auto yval = [&](float tf) -> float {
        float idx = (tf < d) ? (tf * rl) : fmaf(tf - d, rr, s);
        idx = fminf(fmaxf(idx, 0.0f), (float)(NT - 1));
        float y = idx * (1.0f / (float)(NT - 1)) * (float)(NF - 1);
        return fminf(fmaxf(y, 0.0f), (float)(NF - 1));
    };

    // Tile row window (computed redundantly per thread; no smem, no barrier)
    const int Ymin = (int)floorf(yval((float)j_base));
    int nrows = (int)floorf(yval((float)(j_base + TILE_J - 1))) + 3 - Ymin;
    if (nrows > MAX_ROWS) nrows = MAX_ROWS;

    // ---------- build P-tile: x-resample needed rows, all 128 i ----------
    const float* Sb = S + (size_t)b * (size_t)(NF * NT);
    for (int v = t; v < nrows * NF; v += 256) {       // nrows<=8 -> <=4 iters/thread
        const int r  = v >> 7;
        const int i  = v & (NF - 1);
        const int rs = min(Ymin + r, NF - 1);         // border clamp / pad rows

        float x_pix = ((float)i / (float)(NF - 1)) * (float)(NT - 1);
        x_pix = fminf(fmaxf(x_pix, 0.0f), (float)(NT - 1));
        const float x0f = floorf(x_pix);
        const int   x0  = (int)x0f;
        const int   x1  = min(x0 + 1, NT - 1);
        const float wx  = x_pix - x0f;

        const float* row = Sb + (size_t)rs * NT;
        const float v0 = __ldg(row + x0);
        const float v1 = __ldg(row + x1);
        sP[v] = fmaf(wx, v1 - v0, v0);
    }
    __syncthreads();                                  // the only barrier

    // ---------- stream all 128 freq rows x 256 j ----------
    const int tx = t & (TILE_C - 1);                  // chunk within tile (warp-contiguous)
    const int ty = t >> 6;                            // i-offset 0..3

    // Register-resident per-chunk y tables (identical FP sequence to prior rounds)
    float wy0, wy1, wy2, wy3; int Y;
    {
        float y  = yval((float)(j_base + tx * 4));
        float yf = floorf(y);
        wy0 = y - yf;  Y = (int)yf;
        y = yval((float)(j_base + tx * 4 + 1)); wy1 = y - floorf(y);
        y = yval((float)(j_base + tx * 4 + 2)); wy2 = y - floorf(y);
        y = yval((float)(j_base + tx * 4 + 3)); wy3 = y - floorf(y);
    }
    const int rel = Y - Ymin;                         // 0..nrows-3
    const float* pc = sP + rel * NF;

    const bool s1 = wy1 < wy0;                        // floor advanced <=> frac wrapped
    const bool s2 = wy2 < wy0;
    const bool s3 = wy3 < wy0;

    float* obase = out + ((size_t)b * NF) * (size_t)NT + (size_t)(j_base + tx * 4);

#pragma unroll 8
    for (int r = 0; r < NF / 4; r++) {                // 32 iterations
        const int i = r * 4 + ty;

        const float pA = pc[i];
        const float pB = pc[NF + i];
        const float pC = pc[2 * NF + i];

        float o0 = fmaf(wy0, pB - pA, pA);
        float l1 = s1 ? pB : pA, h1 = s1 ? pC : pB;
        float l2 = s2 ? pB : pA, h2 = s2 ? pC : pB;
        float l3 = s3 ? pB : pA, h3 = s3 ? pC : pB;
        float o1 = fmaf(wy1, h1 - l1, l1);
        float o2 = fmaf(wy2, h2 - l2, l2);
        float o3 = fmaf(wy3, h3 - l3, l3);

        __stcs(reinterpret_cast<float4*>(obase + (size_t)i * NT),
               make_float4(o0, o1, o2, o3));
    }
}

extern "C" void kernel_launch(void* const* d_in, const int* in_sizes, int n_in,
                              void* d_out, int out_size)
{
    const float* S    = (const float*)d_in[0];
    const int*   psrc = (const int*)d_in[1];
    const int*   pdst = (const int*)d_in[2];
    float*       out  = (float*)d_out;

    dim3 grid(NT / TILE_J, NB);                       // 32 x 32 = 1024 blocks
    timewarp_fused<<<grid, 256>>>(S, psrc, pdst, out);
}